// round 5
// baseline (speedup 1.0000x reference)
#include <cuda_runtime.h>
#include <cuda_bf16.h>
#include <cstdint>

#define N0 6144
#define DD 320
#define N1 4915
#define N2 2949
#define NNZ_MAX 1900000
#define SORT_N 8192

// ---------------- scratch (__device__ globals; no allocations) ----------------
__device__ float g_h[N0 * DD];
__device__ float g_T[N0 * DD];
__device__ float g_u[N0 * DD];
__device__ float g_v[N0 * DD];
__device__ float g_Xstart[N0 * DD];
__device__ float g_Xfin[N0 * DD];
__device__ float g_down0[N0 * DD];
__device__ float g_down1[N1 * DD];
__device__ float g_cat[N0 * 2 * DD];
__device__ float g_es[N0];
__device__ float g_ed[N0];
__device__ float g_sc[N0];
__device__ unsigned long long g_keys[SORT_N];
__device__ int g_rowcnt[N0];
__device__ int g_rowptr[N0 + 1];
__device__ int g_col[NNZ_MAX];
__device__ int g_idx0[N1];
__device__ int g_gidx1[N1];
__device__ int g_map1[N0];
__device__ int g_idx1[N2];
__device__ int g_gidx2[N2];
__device__ int g_map2[N0];
__device__ int g_idx0f[N1];
__device__ int g_gidx1f[N1];
__device__ int g_map1f[N0];
__device__ int g_idx1f[N2];

// ---------------- CSR build ----------------
__global__ void k_count(const float* __restrict__ A, int* __restrict__ rowcnt) {
    int i = blockIdx.x;
    int c = 0;
    const float* row = A + (size_t)i * N0;
    for (int j = threadIdx.x; j < N0; j += 256) c += (row[j] > 0.f);
    __shared__ int sh[256];
    sh[threadIdx.x] = c; __syncthreads();
    for (int s = 128; s > 0; s >>= 1) {
        if (threadIdx.x < s) sh[threadIdx.x] += sh[threadIdx.x + s];
        __syncthreads();
    }
    if (threadIdx.x == 0) rowcnt[i] = sh[0];
}

__global__ void k_scan(const int* __restrict__ rowcnt, int* __restrict__ rowptr) {
    __shared__ int part[1024];
    int t = threadIdx.x;
    int base = t * 6;
    int loc[6]; int s = 0;
    for (int q = 0; q < 6; q++) { loc[q] = s; s += rowcnt[base + q]; }
    part[t] = s; __syncthreads();
    for (int off = 1; off < 1024; off <<= 1) {
        int v = (t >= off) ? part[t - off] : 0;
        __syncthreads();
        part[t] += v;
        __syncthreads();
    }
    int excl = (t == 0) ? 0 : part[t - 1];
    for (int q = 0; q < 6; q++) rowptr[base + q] = excl + loc[q];
    if (t == 1023) rowptr[N0] = part[1023];
}

__global__ void k_fill(const float* __restrict__ A, const int* __restrict__ rowptr,
                       int* __restrict__ col) {
    int i = blockIdx.x;
    int t = threadIdx.x;   // 256 threads, chunk of 24 cols each
    __shared__ int cnt[256];
    const float* row = A + (size_t)i * N0;
    int c0 = t * 24;
    int c = 0;
    for (int q = 0; q < 24; q++) c += (row[c0 + q] > 0.f);
    cnt[t] = c; __syncthreads();
    for (int off = 1; off < 256; off <<= 1) {
        int v = (t >= off) ? cnt[t - off] : 0;
        __syncthreads();
        cnt[t] += v;
        __syncthreads();
    }
    int pos = rowptr[i] + ((t == 0) ? 0 : cnt[t - 1]);
    for (int q = 0; q < 24; q++)
        if (row[c0 + q] > 0.f) col[pos++] = c0 + q;
}

// ---------------- dense GEMM: C = A[MxK] @ B[KxNc] (+bias)(+res) ----------------
__global__ void k_gemm(const float* __restrict__ A, const float* __restrict__ B,
                       const float* __restrict__ bias, const float* __restrict__ res,
                       float* __restrict__ C, int M, int K, int Nc) {
    __shared__ float As[16][65];
    __shared__ float Bs[16][64];
    int tid = threadIdx.x;
    int tx = tid & 15, ty = tid >> 4;
    int row0 = blockIdx.x * 64, col0 = blockIdx.y * 64;
    float acc[4][4] = {};
    for (int kk = 0; kk < K; kk += 16) {
        #pragma unroll
        for (int l = 0; l < 4; l++) {
            int idx = tid + l * 256;
            int m = idx >> 4, k = idx & 15;
            int r = row0 + m;
            As[k][m] = (r < M) ? A[(size_t)r * K + kk + k] : 0.f;
            int n = idx & 63, k2 = idx >> 6;
            Bs[k2][n] = B[(size_t)(kk + k2) * Nc + col0 + n];
        }
        __syncthreads();
        #pragma unroll
        for (int k = 0; k < 16; k++) {
            float a0 = As[k][ty * 4 + 0];
            float a1 = As[k][ty * 4 + 1];
            float a2 = As[k][ty * 4 + 2];
            float a3 = As[k][ty * 4 + 3];
            float4 b = *(const float4*)&Bs[k][tx * 4];
            acc[0][0] += a0 * b.x; acc[0][1] += a0 * b.y; acc[0][2] += a0 * b.z; acc[0][3] += a0 * b.w;
            acc[1][0] += a1 * b.x; acc[1][1] += a1 * b.y; acc[1][2] += a1 * b.z; acc[1][3] += a1 * b.w;
            acc[2][0] += a2 * b.x; acc[2][1] += a2 * b.y; acc[2][2] += a2 * b.z; acc[2][3] += a2 * b.w;
            acc[3][0] += a3 * b.x; acc[3][1] += a3 * b.y; acc[3][2] += a3 * b.z; acc[3][3] += a3 * b.w;
        }
        __syncthreads();
    }
    #pragma unroll
    for (int i = 0; i < 4; i++) {
        int r = row0 + ty * 4 + i;
        if (r < M) {
            #pragma unroll
            for (int j = 0; j < 4; j++) {
                int c = col0 + tx * 4 + j;
                float v = acc[i][j];
                if (bias) v += bias[c];
                if (res) v += res[(size_t)r * Nc + c];
                C[(size_t)r * Nc + c] = v;
            }
        }
    }
}

// ---------------- SpMM (A restricted to index set) ----------------
__global__ void k_spmm(const int* __restrict__ rowptr, const int* __restrict__ col,
                       const int* __restrict__ gidx, const int* __restrict__ map,
                       const float* __restrict__ Xin, float* __restrict__ Xout, int n) {
    int i = blockIdx.x;
    int t = threadIdx.x;  // 320
    int g = gidx ? gidx[i] : i;
    int s = rowptr[g], e = rowptr[g + 1];
    __shared__ int sj[512];
    float acc = 0.f;
    for (int base = s; base < e; base += 512) {
        int cnt = min(512, e - base);
        __syncthreads();
        for (int q = t; q < cnt; q += 320) {
            int c = col[base + q];
            sj[q] = map ? map[c] : c;
        }
        __syncthreads();
        for (int q = 0; q < cnt; q++) {
            int l = sj[q];
            if (l >= 0) acc += Xin[(size_t)l * DD + t];
        }
    }
    Xout[(size_t)i * DD + t] = acc;
}

// ---------------- fused GAT attention: masked softmax + SpMM + elu ----------------
__global__ void k_gat(const int* __restrict__ rowptr, const int* __restrict__ col,
                      const int* __restrict__ gidx, const int* __restrict__ map,
                      const float* __restrict__ h, const float* __restrict__ es,
                      const float* __restrict__ ed, float* __restrict__ out, int n) {
    int i = blockIdx.x;
    int t = threadIdx.x;  // 320
    int g = gidx ? gidx[i] : i;
    int s0 = rowptr[g], e0 = rowptr[g + 1];
    float esi = es[i];
    __shared__ float redbuf[10];
    __shared__ float smax, sinv;
    __shared__ int sj[512];
    __shared__ float sw[512];

    // phase 1: row max of leaky_relu(es_i + ed_j) over live edges
    float lm = -3e38f;
    for (int q = s0 + t; q < e0; q += 320) {
        int c = col[q];
        int l = map ? map[c] : c;
        if (l >= 0) {
            float v = esi + ed[l];
            v = v > 0.f ? v : 0.2f * v;
            lm = fmaxf(lm, v);
        }
    }
    for (int o = 16; o; o >>= 1) lm = fmaxf(lm, __shfl_xor_sync(0xffffffffu, lm, o));
    if ((t & 31) == 0) redbuf[t >> 5] = lm;
    __syncthreads();
    if (t == 0) {
        float mm = redbuf[0];
        for (int q = 1; q < 10; q++) mm = fmaxf(mm, redbuf[q]);
        smax = mm;
    }
    __syncthreads();
    float m = smax;

    // phase 2: denominator
    float ls = 0.f;
    for (int q = s0 + t; q < e0; q += 320) {
        int c = col[q];
        int l = map ? map[c] : c;
        if (l >= 0) {
            float v = esi + ed[l];
            v = v > 0.f ? v : 0.2f * v;
            ls += expf(v - m);
        }
    }
    for (int o = 16; o; o >>= 1) ls += __shfl_xor_sync(0xffffffffu, ls, o);
    __syncthreads();
    if ((t & 31) == 0) redbuf[t >> 5] = ls;
    __syncthreads();
    if (t == 0) {
        float tt = 0.f;
        for (int q = 0; q < 10; q++) tt += redbuf[q];
        sinv = 1.f / tt;
    }
    __syncthreads();
    float inv = sinv;

    // phase 3: weighted feature accumulation (chunked)
    float acc = 0.f;
    for (int base = s0; base < e0; base += 512) {
        int cnt = min(512, e0 - base);
        __syncthreads();
        for (int q = t; q < cnt; q += 320) {
            int c = col[base + q];
            int l = map ? map[c] : c;
            sj[q] = l;
            if (l >= 0) {
                float v = esi + ed[l];
                v = v > 0.f ? v : 0.2f * v;
                sw[q] = expf(v - m);
            } else sw[q] = 0.f;
        }
        __syncthreads();
        for (int q = 0; q < cnt; q++) {
            int l = sj[q];
            if (l >= 0) acc += sw[q] * h[(size_t)l * DD + t];
        }
    }
    float x = acc * inv;
    out[(size_t)i * DD + t] = x > 0.f ? x : expf(x) - 1.f;
}

// ---------------- small vector kernels ----------------
__global__ void k_attn_vec(const float* __restrict__ h, const float* __restrict__ a,
                           float* __restrict__ es, float* __restrict__ ed, int n) {
    int w = threadIdx.x >> 5, lane = threadIdx.x & 31;
    int row = blockIdx.x * 4 + w;
    if (row >= n) return;
    float s1 = 0.f, s2 = 0.f;
    for (int j = lane; j < DD; j += 32) {
        float hv = h[(size_t)row * DD + j];
        s1 += hv * a[j];
        s2 += hv * a[DD + j];
    }
    for (int o = 16; o; o >>= 1) {
        s1 += __shfl_xor_sync(0xffffffffu, s1, o);
        s2 += __shfl_xor_sync(0xffffffffu, s2, o);
    }
    if (lane == 0) { es[row] = s1; ed[row] = s2; }
}

__global__ void k_scores(const float* __restrict__ X, const float* __restrict__ w,
                         const float* __restrict__ bptr, int bidx,
                         float* __restrict__ sc, int n) {
    int wi = threadIdx.x >> 5, lane = threadIdx.x & 31;
    int row = blockIdx.x * 4 + wi;
    if (row >= n) return;
    float s = 0.f;
    for (int j = lane; j < DD; j += 32) s += X[(size_t)row * DD + j] * w[j];
    for (int o = 16; o; o >>= 1) s += __shfl_xor_sync(0xffffffffu, s, o);
    if (lane == 0) {
        float x = (s + bptr[bidx]) * 0.01f;
        sc[row] = 1.f / (1.f + expf(-x));
    }
}

__global__ void k_keys(const float* __restrict__ sc, unsigned long long* __restrict__ keys, int n) {
    int i = blockIdx.x * 256 + threadIdx.x;
    if (i >= SORT_N) return;
    if (i < n) {
        unsigned int u = __float_as_uint(sc[i]);
        unsigned int ord = (u >> 31) ? ~u : (u | 0x80000000u);
        unsigned int d = ~ord;  // descending
        keys[i] = ((unsigned long long)d << 32) | (unsigned int)i;
    } else {
        keys[i] = 0xFFFFFFFFFFFFFFFFull;
    }
}

// single-block bitonic sort of 8192 keys, ascending
__global__ void k_sort(unsigned long long* __restrict__ keys) {
    for (int kk = 2; kk <= SORT_N; kk <<= 1) {
        for (int j = kk >> 1; j > 0; j >>= 1) {
            for (int t = threadIdx.x; t < SORT_N / 2; t += 1024) {
                int i = ((t / j) * (j << 1)) + (t % j);
                int l = i + j;
                bool asc = ((i & kk) == 0);
                unsigned long long a = keys[i], b = keys[l];
                if ((a > b) == asc) { keys[i] = b; keys[l] = a; }
            }
            __syncthreads();
        }
    }
}

__global__ void k_pool(const unsigned long long* __restrict__ keys, const float* __restrict__ sc,
                       const float* __restrict__ Xin, const int* __restrict__ gidx_in,
                       float* __restrict__ Xout, int* __restrict__ idx_loc,
                       int* __restrict__ gidx_out, int knum) {
    int i = blockIdx.x;
    int t = threadIdx.x;
    int li = (int)(keys[i] & 0xffffffffull);
    float v = sc[li];
    Xout[(size_t)i * DD + t] = Xin[(size_t)li * DD + t] * v;
    if (t == 0) {
        idx_loc[i] = li;
        gidx_out[i] = gidx_in ? gidx_in[li] : li;
    }
}

__global__ void k_map_init(int* __restrict__ map) {
    int i = blockIdx.x * 256 + threadIdx.x;
    if (i < N0) map[i] = -1;
}
__global__ void k_map_set(const int* __restrict__ gidx, int* __restrict__ map, int knum) {
    int i = blockIdx.x * 256 + threadIdx.x;
    if (i < knum) map[gidx[i]] = i;
}

__global__ void k_zero(float* __restrict__ X, int n) {
    int i = blockIdx.x * 256 + threadIdx.x;
    for (; i < n; i += gridDim.x * 256) X[i] = 0.f;
}
__global__ void k_scatter(const float* __restrict__ Xin, const int* __restrict__ idx,
                          float* __restrict__ Xout, int knum) {
    int i = blockIdx.x;
    int t = threadIdx.x;
    Xout[(size_t)idx[i] * DD + t] = Xin[(size_t)i * DD + t];
}
__global__ void k_concat(const float* __restrict__ Xa, const float* __restrict__ Xb,
                         float* __restrict__ Xc) {
    int i = blockIdx.x;
    int t = threadIdx.x;
    Xc[(size_t)i * 2 * DD + t] = Xa[(size_t)i * DD + t];
    Xc[(size_t)i * 2 * DD + DD + t] = Xb[(size_t)i * DD + t];
}
__global__ void k_copyf(float* __restrict__ dst, const float* __restrict__ src, int n) {
    int i = blockIdx.x * 256 + threadIdx.x;
    for (; i < n; i += gridDim.x * 256) dst[i] = src[i];
}
__global__ void k_copyi(int* __restrict__ dst, const int* __restrict__ src, int n) {
    int i = blockIdx.x * 256 + threadIdx.x;
    for (; i < n; i += gridDim.x * 256) dst[i] = src[i];
}

// ---------------- host orchestration ----------------
static void gemm(const float* A, const float* B, const float* bias, const float* res,
                 float* C, int M, int K, int Nc) {
    dim3 grid((M + 63) / 64, Nc / 64);
    k_gemm<<<grid, 256>>>(A, B, bias, res, C, M, K, Nc);
}

template <typename T>
static T* sym_addr(const void* symbol) {
    void* p = nullptr;
    cudaGetSymbolAddress(&p, symbol);
    return (T*)p;
}

extern "C" void kernel_launch(void* const* d_in, const int* in_sizes, int n_in,
                              void* d_out, int out_size) {
    const float* A      = (const float*)d_in[0];
    const float* X      = (const float*)d_in[1];
    const float* sg_W   = (const float*)d_in[2];
    const float* sg_a   = (const float*)d_in[3];
    const float* bg_W   = (const float*)d_in[4];
    const float* bg_a   = (const float*)d_in[5];
    const float* eg_W   = (const float*)d_in[6];
    const float* eg_a   = (const float*)d_in[7];
    const float* down_W = (const float*)d_in[8];
    const float* down_b = (const float*)d_in[9];
    const float* up_W   = (const float*)d_in[10];
    const float* up_b   = (const float*)d_in[11];
    const float* pool_w = (const float*)d_in[12];
    const float* pool_b = (const float*)d_in[13];
    float* outp = (float*)d_out;

    float* p_h      = sym_addr<float>(g_h);
    float* p_T      = sym_addr<float>(g_T);
    float* p_u      = sym_addr<float>(g_u);
    float* p_v      = sym_addr<float>(g_v);
    float* p_Xstart = sym_addr<float>(g_Xstart);
    float* p_Xfin   = sym_addr<float>(g_Xfin);
    float* p_down0  = sym_addr<float>(g_down0);
    float* p_down1  = sym_addr<float>(g_down1);
    float* p_cat    = sym_addr<float>(g_cat);
    float* p_es     = sym_addr<float>(g_es);
    float* p_ed     = sym_addr<float>(g_ed);
    float* p_sc     = sym_addr<float>(g_sc);
    unsigned long long* p_keys = sym_addr<unsigned long long>(g_keys);
    int* p_rowcnt = sym_addr<int>(g_rowcnt);
    int* p_rowptr = sym_addr<int>(g_rowptr);
    int* p_col    = sym_addr<int>(g_col);
    int* p_idx0   = sym_addr<int>(g_idx0);
    int* p_gidx1  = sym_addr<int>(g_gidx1);
    int* p_map1   = sym_addr<int>(g_map1);
    int* p_idx1   = sym_addr<int>(g_idx1);
    int* p_gidx2  = sym_addr<int>(g_gidx2);
    int* p_map2   = sym_addr<int>(g_map2);
    int* p_idx0f  = sym_addr<int>(g_idx0f);
    int* p_gidx1f = sym_addr<int>(g_gidx1f);
    int* p_map1f  = sym_addr<int>(g_map1f);
    int* p_idx1f  = sym_addr<int>(g_idx1f);

    // ---- CSR of A (built every call; deterministic) ----
    k_count<<<N0, 256>>>(A, p_rowcnt);
    k_scan<<<1, 1024>>>(p_rowcnt, p_rowptr);
    k_fill<<<N0, 256>>>(A, p_rowptr, p_col);

    // ---- start GAT ----
    gemm(X, sg_W, nullptr, nullptr, p_h, N0, 320, 320);
    k_attn_vec<<<(N0 + 3) / 4, 128>>>(p_h, sg_a, p_es, p_ed, N0);
    k_gat<<<N0, 320>>>(p_rowptr, p_col, nullptr, nullptr, p_h, p_es, p_ed, p_Xstart, N0);

    for (int pass = 0; pass < 2; pass++) {
        const float* in0 = (pass == 0) ? p_Xstart : p_Xfin;

        // down 0 (level 0)
        k_spmm<<<N0, 320>>>(p_rowptr, p_col, nullptr, nullptr, in0, p_T, N0);
        gemm(p_T, down_W, down_b, nullptr, p_u, N0, 320, 320);
        if (pass == 0) k_copyf<<<512, 256>>>(p_down0, p_u, N0 * DD);

        // pool 0 (k=0.8): 6144 -> 4915
        k_scores<<<(N0 + 3) / 4, 128>>>(p_u, pool_w, pool_b, 0, p_sc, N0);
        k_keys<<<SORT_N / 256, 256>>>(p_sc, p_keys, N0);
        k_sort<<<1, 1024>>>(p_keys);
        k_pool<<<N1, 320>>>(p_keys, p_sc, p_u, nullptr, p_v, p_idx0, p_gidx1, N1);
        k_map_init<<<(N0 + 255) / 256, 256>>>(p_map1);
        k_map_set<<<(N1 + 255) / 256, 256>>>(p_gidx1, p_map1, N1);
        if (pass == 0) {
            k_copyi<<<(N1 + 255) / 256, 256>>>(p_idx0f, p_idx0, N1);
            k_copyi<<<(N1 + 255) / 256, 256>>>(p_gidx1f, p_gidx1, N1);
            k_copyi<<<(N0 + 255) / 256, 256>>>(p_map1f, p_map1, N0);
        }

        // down 1 (level 1)
        k_spmm<<<N1, 320>>>(p_rowptr, p_col, p_gidx1, p_map1, p_v, p_T, N1);
        gemm(p_T, down_W + 320 * 320, down_b + 320, nullptr, p_u, N1, 320, 320);
        if (pass == 0) k_copyf<<<512, 256>>>(p_down1, p_u, N1 * DD);

        // pool 1 (k=0.6): 4915 -> 2949
        k_scores<<<(N1 + 3) / 4, 128>>>(p_u, pool_w + 320, pool_b, 1, p_sc, N1);
        k_keys<<<SORT_N / 256, 256>>>(p_sc, p_keys, N1);
        k_sort<<<1, 1024>>>(p_keys);
        k_pool<<<N2, 320>>>(p_keys, p_sc, p_u, p_gidx1, p_v, p_idx1, p_gidx2, N2);
        k_map_init<<<(N0 + 255) / 256, 256>>>(p_map2);
        k_map_set<<<(N2 + 255) / 256, 256>>>(p_gidx2, p_map2, N2);
        if (pass == 0) k_copyi<<<(N2 + 255) / 256, 256>>>(p_idx1f, p_idx1, N2);

        // bottleneck GAT at level 2
        gemm(p_v, bg_W, nullptr, nullptr, p_h, N2, 320, 320);
        k_attn_vec<<<(N2 + 3) / 4, 128>>>(p_h, bg_a, p_es, p_ed, N2);
        k_gat<<<N2, 320>>>(p_rowptr, p_col, p_gidx2, p_map2, p_h, p_es, p_ed, p_u, N2);

        // up 0: unpool into FIRST-pass level-1 graph, GCN, + first-pass down_out1
        k_zero<<<512, 256>>>(p_v, N1 * DD);
        k_scatter<<<N2, 320>>>(p_u, p_idx1f, p_v, N2);
        k_spmm<<<N1, 320>>>(p_rowptr, p_col, p_gidx1f, p_map1f, p_v, p_T, N1);
        gemm(p_T, up_W, up_b, p_down1, p_u, N1, 320, 320);

        // up 1: unpool into level-0 graph, GCN, + first-pass down_out0
        k_zero<<<512, 256>>>(p_v, N0 * DD);
        k_scatter<<<N1, 320>>>(p_u, p_idx0f, p_v, N1);
        k_spmm<<<N0, 320>>>(p_rowptr, p_col, nullptr, nullptr, p_v, p_T, N0);
        gemm(p_T, up_W + 320 * 320, up_b + 320, p_down0, p_u, N0, 320, 320);

        // concat with org_X then end GAT
        k_concat<<<N0, 320>>>(p_u, p_Xstart, p_cat);
        gemm(p_cat, eg_W, nullptr, nullptr, p_h, N0, 640, 320);
        k_attn_vec<<<(N0 + 3) / 4, 128>>>(p_h, eg_a, p_es, p_ed, N0);
        float* outX = (pass == 0) ? p_Xfin : outp;
        k_gat<<<N0, 320>>>(p_rowptr, p_col, nullptr, nullptr, p_h, p_es, p_ed, outX, N0);
    }

    // second output: start
    if (out_size >= 2 * N0 * DD)
        k_copyf<<<512, 256>>>(outp + (size_t)N0 * DD, p_Xstart, N0 * DD);
}

// round 9
// speedup vs baseline: 1.1313x; 1.1313x over previous
#include <cuda_runtime.h>
#include <cstdint>

#define N0 6144
#define DD 320
#define N1 4915
#define N2 2949
#define NNZ_MAX 1900000
#define SORT_N 8192

// ---------------- scratch (__device__ globals; no allocations) ----------------
__device__ __align__(16) float g_h[N0 * DD];
__device__ __align__(16) float g_T[N0 * DD];
__device__ __align__(16) float g_u[N0 * DD];
__device__ __align__(16) float g_v[N0 * DD];
__device__ __align__(16) float g_Xstart[N0 * DD];
__device__ __align__(16) float g_Xfin[N0 * DD];
__device__ __align__(16) float g_down0[N0 * DD];
__device__ __align__(16) float g_down1[N1 * DD];
__device__ __align__(16) float g_egc[N0 * DD];
__device__ float g_es[N0];
__device__ float g_ed[N0];
__device__ float g_sc[N0];
__device__ unsigned long long g_keys[SORT_N];
__device__ int g_rowcnt[N0];
__device__ int g_rowptr[N0 + 1];
__device__ int g_col[NNZ_MAX];
__device__ int g_idxs[N1];     // scratch idx (per-pool, not persisted)
__device__ int g_gidx1[N1];
__device__ int g_map1[N0];
__device__ int g_gidx2[N2];
__device__ int g_map2[N0];
__device__ int g_gidx1f[N1];
__device__ int g_map1f[N0];
__device__ int g_idx1f[N2];
__device__ int g_imap1f[N1];

// ---------------- CSR build ----------------
__global__ void k_count(const float* __restrict__ A, int* __restrict__ rowcnt) {
    int i = blockIdx.x;
    int c = 0;
    const float* row = A + (size_t)i * N0;
    for (int j = threadIdx.x; j < N0; j += 256) c += (row[j] > 0.f);
    __shared__ int sh[256];
    sh[threadIdx.x] = c; __syncthreads();
    for (int s = 128; s > 0; s >>= 1) {
        if (threadIdx.x < s) sh[threadIdx.x] += sh[threadIdx.x + s];
        __syncthreads();
    }
    if (threadIdx.x == 0) rowcnt[i] = sh[0];
}

__global__ void k_scan(const int* __restrict__ rowcnt, int* __restrict__ rowptr) {
    __shared__ int part[1024];
    int t = threadIdx.x;
    int base = t * 6;
    int loc[6]; int s = 0;
    for (int q = 0; q < 6; q++) { loc[q] = s; s += rowcnt[base + q]; }
    part[t] = s; __syncthreads();
    for (int off = 1; off < 1024; off <<= 1) {
        int v = (t >= off) ? part[t - off] : 0;
        __syncthreads();
        part[t] += v;
        __syncthreads();
    }
    int excl = (t == 0) ? 0 : part[t - 1];
    for (int q = 0; q < 6; q++) rowptr[base + q] = excl + loc[q];
    if (t == 1023) rowptr[N0] = part[1023];
}

__global__ void k_fill(const float* __restrict__ A, const int* __restrict__ rowptr,
                       int* __restrict__ col) {
    int i = blockIdx.x;
    int t = threadIdx.x;
    __shared__ int cnt[256];
    const float* row = A + (size_t)i * N0;
    int c0 = t * 24;
    int c = 0;
    for (int q = 0; q < 24; q++) c += (row[c0 + q] > 0.f);
    cnt[t] = c; __syncthreads();
    for (int off = 1; off < 256; off <<= 1) {
        int v = (t >= off) ? cnt[t - off] : 0;
        __syncthreads();
        cnt[t] += v;
        __syncthreads();
    }
    int pos = rowptr[i] + ((t == 0) ? 0 : cnt[t - 1]);
    for (int q = 0; q < 24; q++)
        if (row[c0 + q] > 0.f) col[pos++] = c0 + q;
}

// ---------- dense GEMM: C = A[MxK] @ B[KxNc] (+bias)(+res); 128x64 tile ----------
// As inner dim 136 keeps each k-row 16B-aligned (136*4 = 544 = 34*16) for the
// float4 (LDS.128) reads in the compute loop.
__global__ void __launch_bounds__(256) k_gemm(
        const float* __restrict__ A, const float* __restrict__ B,
        const float* __restrict__ bias, const float* __restrict__ res,
        float* __restrict__ C, int M, int K, int Nc) {
    __shared__ __align__(16) float As[2][8][136];
    __shared__ __align__(16) float Bs[2][8][64];
    int tid = threadIdx.x;
    int row0 = blockIdx.x * 128, col0 = blockIdx.y * 64;
    int ar = tid >> 1, ac = (tid & 1) * 4;   // A stage: row ar, k ac..ac+3
    int br = tid >> 5, bc = (tid & 31) * 2;  // B stage: k br, col bc..bc+1
    int ty = tid >> 4, tx = tid & 15;        // compute: rows ty*8.., cols tx*4..
    float acc[8][4] = {};
    int nk = K >> 3;
    float4 aReg; float2 bReg;
    {
        int r = row0 + ar;
        aReg = (r < M) ? *(const float4*)&A[(size_t)r * K + ac]
                       : make_float4(0.f, 0.f, 0.f, 0.f);
        bReg = *(const float2*)&B[(size_t)br * Nc + col0 + bc];
        As[0][ac + 0][ar] = aReg.x; As[0][ac + 1][ar] = aReg.y;
        As[0][ac + 2][ar] = aReg.z; As[0][ac + 3][ar] = aReg.w;
        Bs[0][br][bc] = bReg.x; Bs[0][br][bc + 1] = bReg.y;
    }
    __syncthreads();
    int nb = 0;
    for (int kt = 0; kt < nk; kt++) {
        if (kt + 1 < nk) {
            int kk = (kt + 1) << 3;
            int r = row0 + ar;
            aReg = (r < M) ? *(const float4*)&A[(size_t)r * K + kk + ac]
                           : make_float4(0.f, 0.f, 0.f, 0.f);
            bReg = *(const float2*)&B[(size_t)(kk + br) * Nc + col0 + bc];
        }
        #pragma unroll
        for (int k = 0; k < 8; k++) {
            float4 a0 = *(const float4*)&As[nb][k][ty * 8];
            float4 a1 = *(const float4*)&As[nb][k][ty * 8 + 4];
            float4 b  = *(const float4*)&Bs[nb][k][tx * 4];
            float av[8] = {a0.x, a0.y, a0.z, a0.w, a1.x, a1.y, a1.z, a1.w};
            #pragma unroll
            for (int i = 0; i < 8; i++) {
                acc[i][0] += av[i] * b.x; acc[i][1] += av[i] * b.y;
                acc[i][2] += av[i] * b.z; acc[i][3] += av[i] * b.w;
            }
        }
        if (kt + 1 < nk) {
            int o = nb ^ 1;
            As[o][ac + 0][ar] = aReg.x; As[o][ac + 1][ar] = aReg.y;
            As[o][ac + 2][ar] = aReg.z; As[o][ac + 3][ar] = aReg.w;
            Bs[o][br][bc] = bReg.x; Bs[o][br][bc + 1] = bReg.y;
            __syncthreads();
            nb = o;
        }
    }
    #pragma unroll
    for (int i = 0; i < 8; i++) {
        int r = row0 + ty * 8 + i;
        if (r < M) {
            #pragma unroll
            for (int j = 0; j < 4; j++) {
                int c = col0 + tx * 4 + j;
                float v = acc[i][j];
                if (bias) v += bias[c];
                if (res)  v += res[(size_t)r * Nc + c];
                C[(size_t)r * Nc + c] = v;
            }
        }
    }
}

// ------- SpMM on A restricted to index sets; optional two-level index chain -------
__global__ void k_spmm(const int* __restrict__ rowptr, const int* __restrict__ col,
                       const int* __restrict__ gidx, const int* __restrict__ map,
                       const int* __restrict__ imap,
                       const float* __restrict__ Xin, float* __restrict__ Xout, int n) {
    int i = blockIdx.x;
    int t = threadIdx.x;  // 320
    int g = gidx ? gidx[i] : i;
    int s = rowptr[g], e = rowptr[g + 1];
    __shared__ int sj[512];
    float acc = 0.f;
    for (int base = s; base < e; base += 512) {
        int cnt = min(512, e - base);
        __syncthreads();
        for (int q = t; q < cnt; q += 320) {
            int c = col[base + q];
            int l = map ? map[c] : c;
            if (imap && l >= 0) l = imap[l];
            sj[q] = l;
        }
        __syncthreads();
        #pragma unroll 4
        for (int q = 0; q < cnt; q++) {
            int l = sj[q];
            if (l >= 0) acc += Xin[(size_t)l * DD + t];
        }
    }
    Xout[(size_t)i * DD + t] = acc;
}

// ---- fused GAT: online-softmax edge scan + weighted fp32 gather + elu ----
// NOTE: gather stays fp32 — feature magnitudes reach ~3e6 in pass 2, which
// overflows fp16 (inf -> NaN). Do not reintroduce a half-precision h here.
__global__ void k_gat(const int* __restrict__ rowptr, const int* __restrict__ col,
                      const int* __restrict__ gidx, const int* __restrict__ map,
                      const float* __restrict__ h, const float* __restrict__ es,
                      const float* __restrict__ ed, float* __restrict__ out, int n) {
    int i = blockIdx.x;
    int t = threadIdx.x;  // 320
    int g = gidx ? gidx[i] : i;
    int s0 = rowptr[g], e0 = rowptr[g + 1];
    float esi = es[i];
    __shared__ float rm[10], rs[10];
    __shared__ float smax, sinv;
    __shared__ int sj[512];
    __shared__ float sw[512];

    // single pass: online (max, sum) over live edges
    float m = -3e38f, sv = 0.f;
    for (int q = s0 + t; q < e0; q += 320) {
        int c = col[q];
        int l = map ? map[c] : c;
        if (l >= 0) {
            float v = esi + ed[l];
            v = v > 0.f ? v : 0.2f * v;
            if (v > m) { sv = sv * expf(m - v) + 1.f; m = v; }
            else sv += expf(v - m);
        }
    }
    for (int o = 16; o; o >>= 1) {
        float mo = __shfl_xor_sync(0xffffffffu, m, o);
        float so = __shfl_xor_sync(0xffffffffu, sv, o);
        float M2 = fmaxf(m, mo);
        sv = sv * expf(m - M2) + so * expf(mo - M2);
        m = M2;
    }
    if ((t & 31) == 0) { rm[t >> 5] = m; rs[t >> 5] = sv; }
    __syncthreads();
    if (t == 0) {
        float M2 = rm[0], S = rs[0];
        for (int q = 1; q < 10; q++) {
            float Mn = fmaxf(M2, rm[q]);
            S = S * expf(M2 - Mn) + rs[q] * expf(rm[q] - Mn);
            M2 = Mn;
        }
        smax = M2; sinv = 1.f / S;
    }
    __syncthreads();
    float M = smax, inv = sinv;

    // weighted fp32 gather
    float acc = 0.f;
    for (int base = s0; base < e0; base += 512) {
        int cnt = min(512, e0 - base);
        __syncthreads();
        for (int q = t; q < cnt; q += 320) {
            int c = col[base + q];
            int l = map ? map[c] : c;
            sj[q] = l;
            if (l >= 0) {
                float v = esi + ed[l];
                v = v > 0.f ? v : 0.2f * v;
                sw[q] = expf(v - M);
            } else sw[q] = 0.f;
        }
        __syncthreads();
        #pragma unroll 4
        for (int q = 0; q < cnt; q++) {
            int l = sj[q];
            if (l >= 0) acc += sw[q] * h[(size_t)l * DD + t];
        }
    }
    float x = acc * inv;
    out[(size_t)i * DD + t] = x > 0.f ? x : expf(x) - 1.f;
}

// ---------------- small vector kernels ----------------
__global__ void k_attn_vec(const float* __restrict__ h, const float* __restrict__ a,
                           float* __restrict__ es, float* __restrict__ ed, int n) {
    int w = threadIdx.x >> 5, lane = threadIdx.x & 31;
    int row = blockIdx.x * 4 + w;
    if (row >= n) return;
    float s1 = 0.f, s2 = 0.f;
    for (int j = lane; j < DD; j += 32) {
        float hv = h[(size_t)row * DD + j];
        s1 += hv * a[j];
        s2 += hv * a[DD + j];
    }
    for (int o = 16; o; o >>= 1) {
        s1 += __shfl_xor_sync(0xffffffffu, s1, o);
        s2 += __shfl_xor_sync(0xffffffffu, s2, o);
    }
    if (lane == 0) { es[row] = s1; ed[row] = s2; }
}

__global__ void k_scores(const float* __restrict__ X, const float* __restrict__ w,
                         const float* __restrict__ bptr, int bidx,
                         float* __restrict__ sc, int n) {
    int wi = threadIdx.x >> 5, lane = threadIdx.x & 31;
    int row = blockIdx.x * 4 + wi;
    if (row >= n) return;
    float s = 0.f;
    for (int j = lane; j < DD; j += 32) s += X[(size_t)row * DD + j] * w[j];
    for (int o = 16; o; o >>= 1) s += __shfl_xor_sync(0xffffffffu, s, o);
    if (lane == 0) {
        float x = (s + bptr[bidx]) * 0.01f;
        sc[row] = 1.f / (1.f + expf(-x));
    }
}

// ---- SMEM bitonic sort of SORT_N keys (key gen fused); writes top knum keys ----
__global__ void k_sort(const float* __restrict__ sc, int n,
                       unsigned long long* __restrict__ keys_out, int knum) {
    extern __shared__ unsigned long long skeys[];
    int t = threadIdx.x;  // 1024
    for (int i = t; i < SORT_N; i += 1024) {
        unsigned long long kv = ~0ull;
        if (i < n) {
            unsigned int u = __float_as_uint(sc[i]);
            unsigned int ord = (u >> 31) ? ~u : (u | 0x80000000u);
            kv = ((unsigned long long)(~ord) << 32) | (unsigned int)i;  // desc score, asc idx
        }
        skeys[i] = kv;
    }
    __syncthreads();
    for (int kk = 2; kk <= SORT_N; kk <<= 1) {
        for (int j = kk >> 1; j > 0; j >>= 1) {
            #pragma unroll 4
            for (int tt = t; tt < SORT_N / 2; tt += 1024) {
                int i = ((tt & ~(j - 1)) << 1) | (tt & (j - 1));
                int l = i + j;
                bool asc = ((i & kk) == 0);
                unsigned long long a = skeys[i], b = skeys[l];
                if ((a > b) == asc) { skeys[i] = b; skeys[l] = a; }
            }
            __syncthreads();
        }
    }
    for (int i = t; i < knum; i += 1024) keys_out[i] = skeys[i];
}

__global__ void k_pool(const unsigned long long* __restrict__ keys, const float* __restrict__ sc,
                       const float* __restrict__ Xin, const int* __restrict__ gidx_in,
                       float* __restrict__ Xout, int* __restrict__ idx_loc,
                       int* __restrict__ gidx_out, int knum) {
    int i = blockIdx.x;
    int t = threadIdx.x;
    int li = (int)(keys[i] & 0xffffffffull);
    float v = sc[li];
    Xout[(size_t)i * DD + t] = Xin[(size_t)li * DD + t] * v;
    if (t == 0) {
        idx_loc[i] = li;
        gidx_out[i] = gidx_in ? gidx_in[li] : li;
    }
}

__global__ void k_seti(int* __restrict__ p, int v, int n) {
    int i = blockIdx.x * 256 + threadIdx.x;
    if (i < n) p[i] = v;
}
__global__ void k_map_set(const int* __restrict__ src, int* __restrict__ map, int kn) {
    int i = blockIdx.x * 256 + threadIdx.x;
    if (i < kn) map[src[i]] = i;
}
__global__ void k_copyf(float* __restrict__ dst, const float* __restrict__ src, int n) {
    int i = blockIdx.x * 256 + threadIdx.x;
    for (; i < n; i += gridDim.x * 256) dst[i] = src[i];
}

// ---------------- host orchestration ----------------
static void gemm(const float* A, const float* B, const float* bias, const float* res,
                 float* C, int M, int K, int Nc) {
    dim3 grid((M + 127) / 128, Nc / 64);
    k_gemm<<<grid, 256>>>(A, B, bias, res, C, M, K, Nc);
}

template <typename T>
static T* sym_addr(const void* symbol) {
    void* p = nullptr;
    cudaGetSymbolAddress(&p, symbol);
    return (T*)p;
}

extern "C" void kernel_launch(void* const* d_in, const int* in_sizes, int n_in,
                              void* d_out, int out_size) {
    const float* A      = (const float*)d_in[0];
    const float* X      = (const float*)d_in[1];
    const float* sg_W   = (const float*)d_in[2];
    const float* sg_a   = (const float*)d_in[3];
    const float* bg_W   = (const float*)d_in[4];
    const float* bg_a   = (const float*)d_in[5];
    const float* eg_W   = (const float*)d_in[6];
    const float* eg_a   = (const float*)d_in[7];
    const float* down_W = (const float*)d_in[8];
    const float* down_b = (const float*)d_in[9];
    const float* up_W   = (const float*)d_in[10];
    const float* up_b   = (const float*)d_in[11];
    const float* pool_w = (const float*)d_in[12];
    const float* pool_b = (const float*)d_in[13];
    float* outp = (float*)d_out;

    float* p_h      = sym_addr<float>(g_h);
    float* p_T      = sym_addr<float>(g_T);
    float* p_u      = sym_addr<float>(g_u);
    float* p_v      = sym_addr<float>(g_v);
    float* p_Xstart = sym_addr<float>(g_Xstart);
    float* p_Xfin   = sym_addr<float>(g_Xfin);
    float* p_down0  = sym_addr<float>(g_down0);
    float* p_down1  = sym_addr<float>(g_down1);
    float* p_egc    = sym_addr<float>(g_egc);
    float* p_es     = sym_addr<float>(g_es);
    float* p_ed     = sym_addr<float>(g_ed);
    float* p_sc     = sym_addr<float>(g_sc);
    unsigned long long* p_keys = sym_addr<unsigned long long>(g_keys);
    int* p_rowcnt = sym_addr<int>(g_rowcnt);
    int* p_rowptr = sym_addr<int>(g_rowptr);
    int* p_col    = sym_addr<int>(g_col);
    int* p_idxs   = sym_addr<int>(g_idxs);
    int* p_gidx1  = sym_addr<int>(g_gidx1);
    int* p_map1   = sym_addr<int>(g_map1);
    int* p_gidx2  = sym_addr<int>(g_gidx2);
    int* p_map2   = sym_addr<int>(g_map2);
    int* p_gidx1f = sym_addr<int>(g_gidx1f);
    int* p_map1f  = sym_addr<int>(g_map1f);
    int* p_idx1f  = sym_addr<int>(g_idx1f);
    int* p_imap1f = sym_addr<int>(g_imap1f);

    cudaFuncSetAttribute(k_sort, cudaFuncAttributeMaxDynamicSharedMemorySize,
                         SORT_N * sizeof(unsigned long long));

    // ---- CSR of A ----
    k_count<<<N0, 256>>>(A, p_rowcnt);
    k_scan<<<1, 1024>>>(p_rowcnt, p_rowptr);
    k_fill<<<N0, 256>>>(A, p_rowptr, p_col);

    // ---- start GAT ----
    gemm(X, sg_W, nullptr, nullptr, p_h, N0, 320, 320);
    k_attn_vec<<<(N0 + 3) / 4, 128>>>(p_h, sg_a, p_es, p_ed, N0);
    k_gat<<<N0, 320>>>(p_rowptr, p_col, nullptr, nullptr, p_h, p_es, p_ed, p_Xstart, N0);

    // pass-invariant half of the end-GAT projection: org_X @ eg_W[320:,:]
    gemm(p_Xstart, eg_W + 320 * 320, nullptr, nullptr, p_egc, N0, 320, 320);

    for (int pass = 0; pass < 2; pass++) {
        const float* in0 = (pass == 0) ? p_Xstart : p_Xfin;
        int* gidx1c = (pass == 0) ? p_gidx1f : p_gidx1;
        int* map1c  = (pass == 0) ? p_map1f  : p_map1;
        int* idx1c  = (pass == 0) ? p_idx1f  : p_idxs;
        float* d0 = (pass == 0) ? p_down0 : p_u;
        float* d1 = (pass == 0) ? p_down1 : p_u;

        // down 0 (level 0)
        k_spmm<<<N0, 320>>>(p_rowptr, p_col, nullptr, nullptr, nullptr, in0, p_T, N0);
        gemm(p_T, down_W, down_b, nullptr, d0, N0, 320, 320);

        // pool 0 (k=0.8): 6144 -> 4915
        k_scores<<<(N0 + 3) / 4, 128>>>(d0, pool_w, pool_b, 0, p_sc, N0);
        k_sort<<<1, 1024, SORT_N * sizeof(unsigned long long)>>>(p_sc, N0, p_keys, N1);
        k_pool<<<N1, 320>>>(p_keys, p_sc, d0, nullptr, p_v, p_idxs, gidx1c, N1);
        k_seti<<<(N0 + 255) / 256, 256>>>(map1c, -1, N0);
        k_map_set<<<(N1 + 255) / 256, 256>>>(gidx1c, map1c, N1);

        // down 1 (level 1)
        k_spmm<<<N1, 320>>>(p_rowptr, p_col, gidx1c, map1c, nullptr, p_v, p_T, N1);
        gemm(p_T, down_W + 320 * 320, down_b + 320, nullptr, d1, N1, 320, 320);

        // pool 1 (k=0.6): 4915 -> 2949
        k_scores<<<(N1 + 3) / 4, 128>>>(d1, pool_w + 320, pool_b, 1, p_sc, N1);
        k_sort<<<1, 1024, SORT_N * sizeof(unsigned long long)>>>(p_sc, N1, p_keys, N2);
        k_pool<<<N2, 320>>>(p_keys, p_sc, d1, gidx1c, p_v, idx1c, p_gidx2, N2);
        k_seti<<<(N0 + 255) / 256, 256>>>(p_map2, -1, N0);
        k_map_set<<<(N2 + 255) / 256, 256>>>(p_gidx2, p_map2, N2);
        if (pass == 0) {  // inverse of first-pass idx1 (level-1 local -> level-2 local)
            k_seti<<<(N1 + 255) / 256, 256>>>(p_imap1f, -1, N1);
            k_map_set<<<(N2 + 255) / 256, 256>>>(p_idx1f, p_imap1f, N2);
        }

        // bottleneck GAT at level 2
        gemm(p_v, bg_W, nullptr, nullptr, p_h, N2, 320, 320);
        k_attn_vec<<<(N2 + 3) / 4, 128>>>(p_h, bg_a, p_es, p_ed, N2);
        k_gat<<<N2, 320>>>(p_rowptr, p_col, p_gidx2, p_map2, p_h, p_es, p_ed, p_u, N2);

        // up 0: fused unpool (gather compact level-2 X via map chain) + GCN + skip
        k_spmm<<<N1, 320>>>(p_rowptr, p_col, p_gidx1f, p_map1f, p_imap1f, p_u, p_T, N1);
        gemm(p_T, up_W, up_b, p_down1, p_u, N1, 320, 320);

        // up 1: fused unpool (gather compact level-1 X via map1f) + GCN + skip
        k_spmm<<<N0, 320>>>(p_rowptr, p_col, nullptr, p_map1f, nullptr, p_u, p_T, N0);
        gemm(p_T, up_W + 320 * 320, up_b + 320, p_down0, p_u, N0, 320, 320);

        // end GAT: cat@eg_W = up@eg_W_top + org_X@eg_W_bot (precomputed)
        gemm(p_u, eg_W, nullptr, p_egc, p_h, N0, 320, 320);
        k_attn_vec<<<(N0 + 3) / 4, 128>>>(p_h, eg_a, p_es, p_ed, N0);
        float* outX = (pass == 0) ? p_Xfin : outp;
        k_gat<<<N0, 320>>>(p_rowptr, p_col, nullptr, nullptr, p_h, p_es, p_ed, outX, N0);
    }

    // second output: start
    if (out_size >= 2 * N0 * DD)
        k_copyf<<<512, 256>>>(outp + (size_t)N0 * DD, p_Xstart, N0 * DD);
}